// round 4
// baseline (speedup 1.0000x reference)
#include <cuda_runtime.h>
#include <math.h>

// Problem constants
#define BB     4
#define SEQ    2048
#define DMODEL 768
#define NH     12
#define HDIM   64
#define M_TOT  (BB * SEQ)      // 8192
#define N_QKV  (3 * DMODEL)    // 2304

// Scratch (device globals; no runtime allocation allowed)
__device__ float g_Q[BB * NH * SEQ * HDIM];
__device__ float g_K[BB * NH * SEQ * HDIM];
__device__ float g_V[BB * NH * SEQ * HDIM];
__device__ float g_Ctx[BB * SEQ * DMODEL];

// ---------------------------------------------------------------------------
// tf32 helpers
// ---------------------------------------------------------------------------
__device__ __forceinline__ unsigned cvt_tf32(float x) {
    unsigned u;
    asm("cvt.rna.tf32.f32 %0, %1;" : "=r"(u) : "f"(x));
    return u;
}
__device__ __forceinline__ void split_tf32(float x, float& h, float& l) {
    h = __uint_as_float(cvt_tf32(x));
    l = __uint_as_float(cvt_tf32(x - h));
}
__device__ __forceinline__ void mma8(float* c, const unsigned* a, const unsigned* b) {
    asm volatile(
        "mma.sync.aligned.m16n8k8.row.col.f32.tf32.tf32.f32 "
        "{%0,%1,%2,%3},{%4,%5,%6,%7},{%8,%9},{%0,%1,%2,%3};\n"
        : "+f"(c[0]), "+f"(c[1]), "+f"(c[2]), "+f"(c[3])
        : "r"(a[0]), "r"(a[1]), "r"(a[2]), "r"(a[3]), "r"(b[0]), "r"(b[1]));
}
#define FU(x) __float_as_uint(x)

// ---------------------------------------------------------------------------
// GEMM (3xTF32): C = A(MxK) * W(KxN) + bvec
// MODE 0: A = x, scatter into g_Q/g_K/g_V   (N = 2304, K = 768)
// MODE 1: A = g_Ctx, write Cout (+bias)     (N = 768,  K = 768)
// Block 128x64, BK=16, 256 threads; warps 4(M)x2(N), warp tile 32x32.
// ---------------------------------------------------------------------------
template <int MODE>
__global__ void __launch_bounds__(256, 1) gemm_tc(
    const float* __restrict__ A,
    const float* __restrict__ W,
    const float* __restrict__ bvec,
    float* __restrict__ Cout,
    int Ncols, int Kdim)
{
    __shared__ float Ah[16 * 136], Al[16 * 136];
    __shared__ float Bh[16 * 72],  Bl[16 * 72];

    const int tid = threadIdx.x, lane = tid & 31, warp = tid >> 5;
    const int wm = (warp >> 1) * 32, wn = (warp & 1) * 32;
    const int g = lane >> 2, tig = lane & 3;
    const int m0 = blockIdx.y * 128, n0 = blockIdx.x * 64;

    const float* Ap = (MODE == 1) ? g_Ctx : A;

    const int am = tid >> 1, akb = (tid & 1) * 8;
    const int bk = tid >> 4, bn = (tid & 15) * 4;
    const float* Ag = Ap + (size_t)(m0 + am) * Kdim + akb;
    const float* Wg = W + (size_t)bk * Ncols + n0 + bn;

    float c[2][4][4];
#pragma unroll
    for (int mt = 0; mt < 2; mt++)
#pragma unroll
        for (int nt = 0; nt < 4; nt++)
#pragma unroll
            for (int i = 0; i < 4; i++) c[mt][nt][i] = 0.0f;

    float4 pa0 = *(const float4*)(Ag);
    float4 pa1 = *(const float4*)(Ag + 4);
    float4 pb  = *(const float4*)(Wg);

    for (int k0 = 0; k0 < Kdim; k0 += 16) {
        // split + store staged regs
        {
            float av[8] = {pa0.x, pa0.y, pa0.z, pa0.w, pa1.x, pa1.y, pa1.z, pa1.w};
#pragma unroll
            for (int i = 0; i < 8; i++) {
                float h, l; split_tf32(av[i], h, l);
                Ah[(akb + i) * 136 + am] = h;
                Al[(akb + i) * 136 + am] = l;
            }
            float bv[4] = {pb.x, pb.y, pb.z, pb.w};
#pragma unroll
            for (int i = 0; i < 4; i++) {
                float h, l; split_tf32(bv[i], h, l);
                Bh[bk * 72 + bn + i] = h;
                Bl[bk * 72 + bn + i] = l;
            }
        }
        __syncthreads();

        if (k0 + 16 < Kdim) {
            pa0 = *(const float4*)(Ag + k0 + 16);
            pa1 = *(const float4*)(Ag + k0 + 20);
            pb  = *(const float4*)(Wg + (size_t)(k0 + 16) * Ncols);
        }

#pragma unroll
        for (int ks = 0; ks < 2; ks++) {
            const int kb = ks * 8;
            unsigned ah[2][4], al[2][4];
#pragma unroll
            for (int mt = 0; mt < 2; mt++) {
                const int mb = wm + mt * 16 + g;
                ah[mt][0] = FU(Ah[(kb + tig) * 136 + mb]);
                ah[mt][1] = FU(Ah[(kb + tig) * 136 + mb + 8]);
                ah[mt][2] = FU(Ah[(kb + tig + 4) * 136 + mb]);
                ah[mt][3] = FU(Ah[(kb + tig + 4) * 136 + mb + 8]);
                al[mt][0] = FU(Al[(kb + tig) * 136 + mb]);
                al[mt][1] = FU(Al[(kb + tig) * 136 + mb + 8]);
                al[mt][2] = FU(Al[(kb + tig + 4) * 136 + mb]);
                al[mt][3] = FU(Al[(kb + tig + 4) * 136 + mb + 8]);
            }
#pragma unroll
            for (int nt = 0; nt < 4; nt++) {
                const int nb = wn + nt * 8 + g;
                unsigned bh[2], bl[2];
                bh[0] = FU(Bh[(kb + tig) * 72 + nb]);
                bh[1] = FU(Bh[(kb + tig + 4) * 72 + nb]);
                bl[0] = FU(Bl[(kb + tig) * 72 + nb]);
                bl[1] = FU(Bl[(kb + tig + 4) * 72 + nb]);
#pragma unroll
                for (int mt = 0; mt < 2; mt++) {
                    mma8(c[mt][nt], ah[mt], bh);
                    mma8(c[mt][nt], ah[mt], bl);
                    mma8(c[mt][nt], al[mt], bh);
                }
            }
        }
        __syncthreads();
    }

    // epilogue
    if (MODE == 0) {
        const int t = n0 / DMODEL;
        const int hh = (n0 % DMODEL) / HDIM;
        const int bidx = m0 / SEQ;
        const int ns0 = m0 % SEQ;
        float* dst = (t == 0) ? g_Q : ((t == 1) ? g_K : g_V);
        float* base = dst + ((size_t)bidx * NH + hh) * SEQ * HDIM;
#pragma unroll
        for (int mt = 0; mt < 2; mt++)
#pragma unroll
            for (int nt = 0; nt < 4; nt++) {
                const int hd = wn + nt * 8 + 2 * tig;
                const float b0 = bvec[n0 + hd], b1 = bvec[n0 + hd + 1];
                const int r = ns0 + wm + mt * 16 + g;
                *(float2*)(base + (size_t)r * HDIM + hd) =
                    make_float2(c[mt][nt][0] + b0, c[mt][nt][1] + b1);
                *(float2*)(base + (size_t)(r + 8) * HDIM + hd) =
                    make_float2(c[mt][nt][2] + b0, c[mt][nt][3] + b1);
            }
    } else {
#pragma unroll
        for (int mt = 0; mt < 2; mt++)
#pragma unroll
            for (int nt = 0; nt < 4; nt++) {
                const int ncol = n0 + wn + nt * 8 + 2 * tig;
                const float b0 = bvec[ncol], b1 = bvec[ncol + 1];
                const int r = m0 + wm + mt * 16 + g;
                *(float2*)(Cout + (size_t)r * Ncols + ncol) =
                    make_float2(c[mt][nt][0] + b0, c[mt][nt][1] + b1);
                *(float2*)(Cout + (size_t)(r + 8) * Ncols + ncol) =
                    make_float2(c[mt][nt][2] + b0, c[mt][nt][3] + b1);
            }
    }
}

// ---------------------------------------------------------------------------
// Flash attention, 3xTF32 mma. Block = 128 q rows, 8 warps (16 rows each),
// KV tiles of 64. SMEM: Kh/Kl/Vh/Vl [64][72], Ph/Pl [64][136].
// ---------------------------------------------------------------------------
#define AT_SMEM ((4 * 64 * 72 + 2 * 64 * 136) * 4)

__global__ void __launch_bounds__(256, 1) attn_tc(const float* __restrict__ bias)
{
    extern __shared__ float sm[];
    float* Kh = sm;
    float* Kl = Kh + 64 * 72;
    float* Vh = Kl + 64 * 72;
    float* Vl = Vh + 64 * 72;
    float* Ph = Vl + 64 * 72;
    float* Pl = Ph + 64 * 136;

    const int tid = threadIdx.x, lane = tid & 31, w = tid >> 5;
    const int g = lane >> 2, tig = lane & 3;
    const int q0 = blockIdx.x * 128, h = blockIdx.y, b = blockIdx.z;

    const float* Qg = g_Q + ((size_t)b * NH + h) * SEQ * HDIM;
    const float* Kg = g_K + ((size_t)b * NH + h) * SEQ * HDIM;
    const float* Vg = g_V + ((size_t)b * NH + h) * SEQ * HDIM;
    const float* biasg = bias + ((size_t)h * SEQ + q0 + 16 * w) * SEQ;

    // stage Q transposed [d][qrow] into Ph (stride 136)
    {
        const int qr = tid >> 1, db = (tid & 1) * 32;
        const float* src = Qg + (size_t)(q0 + qr) * HDIM + db;
#pragma unroll
        for (int u = 0; u < 8; u++) {
            float4 v = *(const float4*)(src + u * 4);
            Ph[(db + u * 4 + 0) * 136 + qr] = v.x;
            Ph[(db + u * 4 + 1) * 136 + qr] = v.y;
            Ph[(db + u * 4 + 2) * 136 + qr] = v.z;
            Ph[(db + u * 4 + 3) * 136 + qr] = v.w;
        }
    }
    __syncthreads();

    // Q fragments (hi/lo) held in registers
    unsigned qh[8][4], ql[8][4];
#pragma unroll
    for (int kt = 0; kt < 8; kt++) {
        const int kr = kt * 8 + tig;
        float f[4];
        f[0] = Ph[kr * 136 + 16 * w + g];
        f[1] = Ph[kr * 136 + 16 * w + g + 8];
        f[2] = Ph[(kr + 4) * 136 + 16 * w + g];
        f[3] = Ph[(kr + 4) * 136 + 16 * w + g + 8];
#pragma unroll
        for (int i = 0; i < 4; i++) {
            float hv, lv; split_tf32(f[i], hv, lv);
            qh[kt][i] = FU(hv); ql[kt][i] = FU(lv);
        }
    }
    __syncthreads();

    float o[8][4];
#pragma unroll
    for (int nt = 0; nt < 8; nt++)
#pragma unroll
        for (int i = 0; i < 4; i++) o[nt][i] = 0.0f;
    float mi[2] = {-1e30f, -1e30f}, li[2] = {0.0f, 0.0f};

    const int token = tid >> 2, dseg = (tid & 3) * 16;
    const float* Krow = Kg + (size_t)token * HDIM + dseg;
    const float* Vrow = Vg + (size_t)token * HDIM + dseg;

    for (int j0 = 0; j0 < SEQ; j0 += 64) {
        // S accumulators pre-initialized with 8*bias (scale folded later)
        float c[8][4];
#pragma unroll
        for (int nt = 0; nt < 8; nt++) {
            const float* bp = biasg + j0 + nt * 8 + 2 * tig;
            float2 b0 = *(const float2*)(bp + (size_t)g * SEQ);
            float2 b1 = *(const float2*)(bp + (size_t)(g + 8) * SEQ);
            c[nt][0] = b0.x * 8.0f; c[nt][1] = b0.y * 8.0f;
            c[nt][2] = b1.x * 8.0f; c[nt][3] = b1.y * 8.0f;
        }
        // load + split K/V tile
#pragma unroll
        for (int u = 0; u < 4; u++) {
            float4 kv = *(const float4*)(Krow + (size_t)j0 * HDIM + u * 4);
            float kf[4] = {kv.x, kv.y, kv.z, kv.w};
#pragma unroll
            for (int i = 0; i < 4; i++) {
                float hv, lv; split_tf32(kf[i], hv, lv);
                Kh[(dseg + u * 4 + i) * 72 + token] = hv;
                Kl[(dseg + u * 4 + i) * 72 + token] = lv;
            }
            float4 vv = *(const float4*)(Vrow + (size_t)j0 * HDIM + u * 4);
            float4 hv4, lv4;
            split_tf32(vv.x, hv4.x, lv4.x);
            split_tf32(vv.y, hv4.y, lv4.y);
            split_tf32(vv.z, hv4.z, lv4.z);
            split_tf32(vv.w, hv4.w, lv4.w);
            *(float4*)&Vh[token * 72 + dseg + u * 4] = hv4;
            *(float4*)&Vl[token * 72 + dseg + u * 4] = lv4;
        }
        __syncthreads();

        // S += Q K^T
#pragma unroll
        for (int kt = 0; kt < 8; kt++) {
            const int kr = kt * 8 + tig;
#pragma unroll
            for (int nt = 0; nt < 8; nt++) {
                const int nb = nt * 8 + g;
                unsigned bh[2], bl[2];
                bh[0] = FU(Kh[kr * 72 + nb]);
                bh[1] = FU(Kh[(kr + 4) * 72 + nb]);
                bl[0] = FU(Kl[kr * 72 + nb]);
                bl[1] = FU(Kl[(kr + 4) * 72 + nb]);
                mma8(c[nt], qh[kt], bh);
                mma8(c[nt], qh[kt], bl);
                mma8(c[nt], ql[kt], bh);
            }
        }

        // online softmax (rows g, g+8)
        float alpha[2];
#pragma unroll
        for (int r = 0; r < 2; r++) {
            const int e0 = r * 2;
            float mx = -1e30f;
#pragma unroll
            for (int nt = 0; nt < 8; nt++)
                mx = fmaxf(mx, fmaxf(c[nt][e0], c[nt][e0 + 1]));
            mx = fmaxf(mx, __shfl_xor_sync(0xffffffffu, mx, 1));
            mx = fmaxf(mx, __shfl_xor_sync(0xffffffffu, mx, 2));
            const float mn = fmaxf(mi[r], mx * 0.125f);
            alpha[r] = __expf(mi[r] - mn);
            mi[r] = mn;
            float rs = 0.0f;
#pragma unroll
            for (int nt = 0; nt < 8; nt++) {
                float p0 = __expf(fmaf(c[nt][e0], 0.125f, -mn));
                float p1 = __expf(fmaf(c[nt][e0 + 1], 0.125f, -mn));
                c[nt][e0] = p0; c[nt][e0 + 1] = p1;
                rs += p0 + p1;
            }
            rs += __shfl_xor_sync(0xffffffffu, rs, 1);
            rs += __shfl_xor_sync(0xffffffffu, rs, 2);
            li[r] = li[r] * alpha[r] + rs;
#pragma unroll
            for (int nt = 0; nt < 8; nt++) {
                o[nt][e0]     *= alpha[r];
                o[nt][e0 + 1] *= alpha[r];
            }
        }

        // store P (split) to SMEM [token][qrow]
#pragma unroll
        for (int nt = 0; nt < 8; nt++)
#pragma unroll
            for (int e = 0; e < 2; e++) {
                const int col = nt * 8 + 2 * tig + e;
                float hv, lv;
                split_tf32(c[nt][e], hv, lv);
                Ph[col * 136 + 16 * w + g] = hv;
                Pl[col * 136 + 16 * w + g] = lv;
                split_tf32(c[nt][2 + e], hv, lv);
                Ph[col * 136 + 16 * w + g + 8] = hv;
                Pl[col * 136 + 16 * w + g + 8] = lv;
            }
        __syncthreads();

        // O += P V
#pragma unroll
        for (int kt = 0; kt < 8; kt++) {
            const int kr = kt * 8 + tig;
            unsigned ph[4], pl[4];
            ph[0] = FU(Ph[kr * 136 + 16 * w + g]);
            ph[1] = FU(Ph[kr * 136 + 16 * w + g + 8]);
            ph[2] = FU(Ph[(kr + 4) * 136 + 16 * w + g]);
            ph[3] = FU(Ph[(kr + 4) * 136 + 16 * w + g + 8]);
            pl[0] = FU(Pl[kr * 136 + 16 * w + g]);
            pl[1] = FU(Pl[kr * 136 + 16 * w + g + 8]);
            pl[2] = FU(Pl[(kr + 4) * 136 + 16 * w + g]);
            pl[3] = FU(Pl[(kr + 4) * 136 + 16 * w + g + 8]);
#pragma unroll
            for (int nt = 0; nt < 8; nt++) {
                const int nb = nt * 8 + g;
                unsigned bh[2], bl[2];
                bh[0] = FU(Vh[kr * 72 + nb]);
                bh[1] = FU(Vh[(kr + 4) * 72 + nb]);
                bl[0] = FU(Vl[kr * 72 + nb]);
                bl[1] = FU(Vl[(kr + 4) * 72 + nb]);
                mma8(o[nt], ph, bh);
                mma8(o[nt], ph, bl);
                mma8(o[nt], pl, bh);
            }
        }
        __syncthreads();
    }

    // epilogue
    float* Cg = g_Ctx + ((size_t)b * SEQ + q0 + 16 * w) * DMODEL + h * HDIM;
#pragma unroll
    for (int r = 0; r < 2; r++) {
        const float inv = 1.0f / li[r];
        float* rp = Cg + (size_t)(g + 8 * r) * DMODEL;
#pragma unroll
        for (int nt = 0; nt < 8; nt++)
            *(float2*)(rp + nt * 8 + 2 * tig) =
                make_float2(o[nt][r * 2] * inv, o[nt][r * 2 + 1] * inv);
    }
}

// ---------------------------------------------------------------------------
extern "C" void kernel_launch(void* const* d_in, const int* in_sizes, int n_in,
                              void* d_out, int out_size)
{
    const float* x     = (const float*)d_in[0];
    const float* bias  = (const float*)d_in[1];
    const float* Wqkv  = (const float*)d_in[2];
    const float* bqkv  = (const float*)d_in[3];
    const float* Wproj = (const float*)d_in[4];
    const float* bproj = (const float*)d_in[5];
    float* out = (float*)d_out;

    cudaFuncSetAttribute(attn_tc,
                         cudaFuncAttributeMaxDynamicSharedMemorySize, AT_SMEM);

    {
        dim3 grid(N_QKV / 64, M_TOT / 128);
        gemm_tc<0><<<grid, 256>>>(x, Wqkv, bqkv, nullptr, N_QKV, DMODEL);
    }
    {
        dim3 grid(SEQ / 128, NH, BB);
        attn_tc<<<grid, 256, AT_SMEM>>>(bias);
    }
    {
        dim3 grid(DMODEL / 64, M_TOT / 128);
        gemm_tc<1><<<grid, 256>>>(nullptr, Wproj, bproj, out, DMODEL, DMODEL);
    }
}

// round 7
// speedup vs baseline: 1.7301x; 1.7301x over previous
#include <cuda_runtime.h>
#include <cuda_bf16.h>
#include <math.h>

// Problem constants
#define BB     4
#define SEQ    2048
#define DMODEL 768
#define NH     12
#define HDIM   64
#define M_TOT  (BB * SEQ)      // 8192
#define N_QKV  (3 * DMODEL)    // 2304

// Scratch (device globals; no runtime allocation allowed)
__device__ float g_Q[BB * NH * SEQ * HDIM];
__device__ float g_K[BB * NH * SEQ * HDIM];
__device__ float g_V[BB * NH * SEQ * HDIM];
__device__ float g_Ctx[BB * SEQ * DMODEL];

// ---------------------------------------------------------------------------
// bf16 helpers: x = hi + lo, products hi*hi + hi*lo + lo*hi (drop lo*lo)
// ---------------------------------------------------------------------------
__device__ __forceinline__ float bhi(float x) {
    return __bfloat162float(__float2bfloat16(x));
}
// pack two elements (e0 = lower/even k, e1 = upper/odd k) as bf16x2
__device__ __forceinline__ unsigned bpack(float e0, float e1) {
    unsigned r;
    asm("cvt.rn.bf16x2.f32 %0, %1, %2;" : "=r"(r) : "f"(e1), "f"(e0));
    return r;
}
__device__ __forceinline__ void mma16(float* c, const unsigned* a, const unsigned* b) {
    asm volatile(
        "mma.sync.aligned.m16n8k16.row.col.f32.bf16.bf16.f32 "
        "{%0,%1,%2,%3},{%4,%5,%6,%7},{%8,%9},{%0,%1,%2,%3};\n"
        : "+f"(c[0]), "+f"(c[1]), "+f"(c[2]), "+f"(c[3])
        : "r"(a[0]), "r"(a[1]), "r"(a[2]), "r"(a[3]), "r"(b[0]), "r"(b[1]));
}

// ---------------------------------------------------------------------------
// GEMM (3xBF16): C = A(MxK) * W(KxN) + bvec
// MODE 0: A = x, scatter into g_Q/g_K/g_V   (N = 2304, K = 768)
// MODE 1: A = g_Ctx, write Cout (+bias)     (N = 768,  K = 768)
// Block 128x64, BK=32, 256 threads; warps 4(M)x2(N), warp tile 32x32.
// SMEM holds bf16x2 k-pairs: Ah/Al [16 kpairs][128m +pad], Bh/Bl [16][64+pad].
// ---------------------------------------------------------------------------
template <int MODE>
__global__ void __launch_bounds__(256, 2) gemm_tc(
    const float* __restrict__ A,
    const float* __restrict__ W,
    const float* __restrict__ bvec,
    float* __restrict__ Cout,
    int Ncols, int Kdim)
{
    __shared__ __align__(16) unsigned Ah[16 * 136], Al[16 * 136];
    __shared__ __align__(16) unsigned Bh[16 * 72],  Bl[16 * 72];

    const int tid = threadIdx.x, lane = tid & 31, warp = tid >> 5;
    const int wm = (warp >> 1) * 32, wn = (warp & 1) * 32;
    const int g = lane >> 2, tig = lane & 3;
    const int m0 = blockIdx.y * 128, n0 = blockIdx.x * 64;

    const float* Ap = (MODE == 1) ? g_Ctx : A;

    // A load map: row am = tid>>1 (0..127), k offset ak = 0/16 -> 4 float4
    const int am = tid >> 1, ak = (tid & 1) * 16;
    // B load map: kpair pk = tid>>4 (0..15), cols bn..bn+3
    const int pk = tid >> 4, bn = (tid & 15) * 4;
    const float* Ag  = Ap + (size_t)(m0 + am) * Kdim + ak;
    const float* Wg0 = W + (size_t)(2 * pk) * Ncols + n0 + bn;   // even k row
    const float* Wg1 = Wg0 + Ncols;                               // odd k row

    float c[2][4][4];
#pragma unroll
    for (int mt = 0; mt < 2; mt++)
#pragma unroll
        for (int nt = 0; nt < 4; nt++)
#pragma unroll
            for (int i = 0; i < 4; i++) c[mt][nt][i] = 0.0f;

    float4 pa[4];
#pragma unroll
    for (int u = 0; u < 4; u++) pa[u] = *(const float4*)(Ag + u * 4);
    float4 pb0 = *(const float4*)(Wg0);
    float4 pb1 = *(const float4*)(Wg1);

    for (int k0 = 0; k0 < Kdim; k0 += 32) {
        // split + pack + store staged regs
        {
            const float* af = (const float*)pa;
            const int kp0 = ak >> 1;
#pragma unroll
            for (int i = 0; i < 8; i++) {
                float x0 = af[2 * i], x1 = af[2 * i + 1];
                float h0 = bhi(x0), h1 = bhi(x1);
                Ah[(kp0 + i) * 136 + am] = bpack(h0, h1);
                Al[(kp0 + i) * 136 + am] = bpack(x0 - h0, x1 - h1);
            }
            const float* b0f = (const float*)&pb0;
            const float* b1f = (const float*)&pb1;
            unsigned th[4], tl[4];
#pragma unroll
            for (int j = 0; j < 4; j++) {
                float x0 = b0f[j], x1 = b1f[j];   // x0 = even k (lower)
                float h0 = bhi(x0), h1 = bhi(x1);
                th[j] = bpack(h0, h1);
                tl[j] = bpack(x0 - h0, x1 - h1);
            }
            *(uint4*)&Bh[pk * 72 + bn] = *(uint4*)th;
            *(uint4*)&Bl[pk * 72 + bn] = *(uint4*)tl;
        }
        __syncthreads();

        if (k0 + 32 < Kdim) {
#pragma unroll
            for (int u = 0; u < 4; u++)
                pa[u] = *(const float4*)(Ag + k0 + 32 + u * 4);
            pb0 = *(const float4*)(Wg0 + (size_t)(k0 + 32) * Ncols);
            pb1 = *(const float4*)(Wg1 + (size_t)(k0 + 32) * Ncols);
        }

#pragma unroll
        for (int ks = 0; ks < 2; ks++) {
            const int kb = ks * 8;   // kpair base for this k16 step
            unsigned ah[2][4], al[2][4];
#pragma unroll
            for (int mt = 0; mt < 2; mt++) {
                const int mb = wm + mt * 16 + g;
                ah[mt][0] = Ah[(kb + tig) * 136 + mb];
                ah[mt][1] = Ah[(kb + tig) * 136 + mb + 8];
                ah[mt][2] = Ah[(kb + 4 + tig) * 136 + mb];
                ah[mt][3] = Ah[(kb + 4 + tig) * 136 + mb + 8];
                al[mt][0] = Al[(kb + tig) * 136 + mb];
                al[mt][1] = Al[(kb + tig) * 136 + mb + 8];
                al[mt][2] = Al[(kb + 4 + tig) * 136 + mb];
                al[mt][3] = Al[(kb + 4 + tig) * 136 + mb + 8];
            }
#pragma unroll
            for (int nt = 0; nt < 4; nt++) {
                const int nb = wn + nt * 8 + g;
                unsigned bh[2], bl[2];
                bh[0] = Bh[(kb + tig) * 72 + nb];
                bh[1] = Bh[(kb + 4 + tig) * 72 + nb];
                bl[0] = Bl[(kb + tig) * 72 + nb];
                bl[1] = Bl[(kb + 4 + tig) * 72 + nb];
#pragma unroll
                for (int mt = 0; mt < 2; mt++) {
                    mma16(c[mt][nt], ah[mt], bh);
                    mma16(c[mt][nt], ah[mt], bl);
                    mma16(c[mt][nt], al[mt], bh);
                }
            }
        }
        __syncthreads();
    }

    // epilogue
    if (MODE == 0) {
        const int t = n0 / DMODEL;
        const int hh = (n0 % DMODEL) / HDIM;
        const int bidx = m0 / SEQ;
        const int ns0 = m0 % SEQ;
        float* dst = (t == 0) ? g_Q : ((t == 1) ? g_K : g_V);
        float* base = dst + ((size_t)bidx * NH + hh) * SEQ * HDIM;
#pragma unroll
        for (int mt = 0; mt < 2; mt++)
#pragma unroll
            for (int nt = 0; nt < 4; nt++) {
                const int hd = wn + nt * 8 + 2 * tig;
                const float b0 = bvec[n0 + hd], b1 = bvec[n0 + hd + 1];
                const int r = ns0 + wm + mt * 16 + g;
                *(float2*)(base + (size_t)r * HDIM + hd) =
                    make_float2(c[mt][nt][0] + b0, c[mt][nt][1] + b1);
                *(float2*)(base + (size_t)(r + 8) * HDIM + hd) =
                    make_float2(c[mt][nt][2] + b0, c[mt][nt][3] + b1);
            }
    } else {
#pragma unroll
        for (int mt = 0; mt < 2; mt++)
#pragma unroll
            for (int nt = 0; nt < 4; nt++) {
                const int ncol = n0 + wn + nt * 8 + 2 * tig;
                const float b0 = bvec[ncol], b1 = bvec[ncol + 1];
                const int r = m0 + wm + mt * 16 + g;
                *(float2*)(Cout + (size_t)r * Ncols + ncol) =
                    make_float2(c[mt][nt][0] + b0, c[mt][nt][1] + b1);
                *(float2*)(Cout + (size_t)(r + 8) * Ncols + ncol) =
                    make_float2(c[mt][nt][2] + b0, c[mt][nt][3] + b1);
            }
    }
}

// ---------------------------------------------------------------------------
// Flash attention, 3xBF16 mma. Block = 128 q rows, 8 warps (16 rows each),
// KV tiles of 64. Q fragments from GMEM; P stays in registers (C->A reuse).
// SMEM: Ksh/Ksl [32 dpairs][64 tok +pad], Vsh/Vsl [32 tpairs][64 dim +pad].
// ---------------------------------------------------------------------------
#define AT_SMEM (4 * 32 * 72 * 4)   // 36864 bytes

__global__ void __launch_bounds__(256) attn_tc(const float* __restrict__ bias)
{
    extern __shared__ __align__(16) unsigned smu[];
    unsigned* Ksh = smu;
    unsigned* Ksl = Ksh + 32 * 72;
    unsigned* Vsh = Ksl + 32 * 72;
    unsigned* Vsl = Vsh + 32 * 72;

    const int tid = threadIdx.x, lane = tid & 31, w = tid >> 5;
    const int g = lane >> 2, tig = lane & 3;
    const int q0 = blockIdx.x * 128, h = blockIdx.y, b = blockIdx.z;

    const float* Qg = g_Q + ((size_t)b * NH + h) * SEQ * HDIM;
    const float* Kg = g_K + ((size_t)b * NH + h) * SEQ * HDIM;
    const float* Vg = g_V + ((size_t)b * NH + h) * SEQ * HDIM;
    const float* biasg = bias + ((size_t)h * SEQ + q0 + 16 * w) * SEQ;

    // Q fragments (hi/lo) straight from global: rows 16w+g, 16w+g+8
    unsigned qh[4][4], ql[4][4];
    {
        const float* r0 = Qg + (size_t)(q0 + 16 * w + g) * HDIM;
        const float* r1 = r0 + 8 * HDIM;
#pragma unroll
        for (int s = 0; s < 4; s++) {
            const int c0 = 16 * s + 2 * tig, c1 = c0 + 8;
            float2 v;
            v = *(const float2*)(r0 + c0);
            { float h0 = bhi(v.x), h1 = bhi(v.y);
              qh[s][0] = bpack(h0, h1); ql[s][0] = bpack(v.x - h0, v.y - h1); }
            v = *(const float2*)(r1 + c0);
            { float h0 = bhi(v.x), h1 = bhi(v.y);
              qh[s][1] = bpack(h0, h1); ql[s][1] = bpack(v.x - h0, v.y - h1); }
            v = *(const float2*)(r0 + c1);
            { float h0 = bhi(v.x), h1 = bhi(v.y);
              qh[s][2] = bpack(h0, h1); ql[s][2] = bpack(v.x - h0, v.y - h1); }
            v = *(const float2*)(r1 + c1);
            { float h0 = bhi(v.x), h1 = bhi(v.y);
              qh[s][3] = bpack(h0, h1); ql[s][3] = bpack(v.x - h0, v.y - h1); }
        }
    }

    float o[8][4];
#pragma unroll
    for (int nt = 0; nt < 8; nt++)
#pragma unroll
        for (int i = 0; i < 4; i++) o[nt][i] = 0.0f;
    float mi[2] = {-1e30f, -1e30f}, li[2] = {0.0f, 0.0f};

    // K fill map: token tk = tid&63, dim-quarter dh = tid>>6
    const int tk = tid & 63, dh = tid >> 6;
    const float* Kp = Kg + (size_t)tk * HDIM + dh * 16;
    // V fill map: token-pair pt = tid>>3, dims dd..dd+7
    const int pt = tid >> 3, dd = (tid & 7) * 8;
    const float* Vp0 = Vg + (size_t)(2 * pt) * HDIM + dd;
    const float* Vp1 = Vp0 + HDIM;

    for (int j0 = 0; j0 < SEQ; j0 += 64) {
        // prefetch K/V tile into regs (before sync)
        float4 kr[4];
#pragma unroll
        for (int u = 0; u < 4; u++)
            kr[u] = *(const float4*)(Kp + (size_t)j0 * HDIM + u * 4);
        float4 vr0[2], vr1[2];
        vr0[0] = *(const float4*)(Vp0 + (size_t)j0 * HDIM);
        vr0[1] = *(const float4*)(Vp0 + (size_t)j0 * HDIM + 4);
        vr1[0] = *(const float4*)(Vp1 + (size_t)j0 * HDIM);
        vr1[1] = *(const float4*)(Vp1 + (size_t)j0 * HDIM + 4);

        // S accumulators pre-initialized with 8*bias (scale folded later)
        float c[8][4];
#pragma unroll
        for (int nt = 0; nt < 8; nt++) {
            const float* bp = biasg + j0 + nt * 8 + 2 * tig;
            float2 b0 = *(const float2*)(bp + (size_t)g * SEQ);
            float2 b1 = *(const float2*)(bp + (size_t)(g + 8) * SEQ);
            c[nt][0] = b0.x * 8.0f; c[nt][1] = b0.y * 8.0f;
            c[nt][2] = b1.x * 8.0f; c[nt][3] = b1.y * 8.0f;
        }
        __syncthreads();   // previous tile fully consumed

        // store K: pairs along dim -> Ksh[(dh*8+i)*72 + tk]
        {
            const float* kf = (const float*)kr;
#pragma unroll
            for (int i = 0; i < 8; i++) {
                float x0 = kf[2 * i], x1 = kf[2 * i + 1];
                float h0 = bhi(x0), h1 = bhi(x1);
                Ksh[(dh * 8 + i) * 72 + tk] = bpack(h0, h1);
                Ksl[(dh * 8 + i) * 72 + tk] = bpack(x0 - h0, x1 - h1);
            }
        }
        // store V: pairs along token -> Vsh[pt*72 + dd + j]
        {
            const float* v0f = (const float*)vr0;
            const float* v1f = (const float*)vr1;
            unsigned th[8], tl[8];
#pragma unroll
            for (int j = 0; j < 8; j++) {
                float x0 = v0f[j], x1 = v1f[j];   // x0 = even token (lower)
                float h0 = bhi(x0), h1 = bhi(x1);
                th[j] = bpack(h0, h1);
                tl[j] = bpack(x0 - h0, x1 - h1);
            }
            *(uint4*)&Vsh[pt * 72 + dd]     = *(uint4*)&th[0];
            *(uint4*)&Vsh[pt * 72 + dd + 4] = *(uint4*)&th[4];
            *(uint4*)&Vsl[pt * 72 + dd]     = *(uint4*)&tl[0];
            *(uint4*)&Vsl[pt * 72 + dd + 4] = *(uint4*)&tl[4];
        }
        __syncthreads();

        // S += Q K^T   (k = dims, 4 k16-steps; n = 64 tokens)
#pragma unroll
        for (int s = 0; s < 4; s++) {
            const int kb = s * 8;
#pragma unroll
            for (int nt = 0; nt < 8; nt++) {
                const int nb = nt * 8 + g;
                unsigned bh[2], bl[2];
                bh[0] = Ksh[(kb + tig) * 72 + nb];
                bh[1] = Ksh[(kb + 4 + tig) * 72 + nb];
                bl[0] = Ksl[(kb + tig) * 72 + nb];
                bl[1] = Ksl[(kb + 4 + tig) * 72 + nb];
                mma16(c[nt], qh[s], bh);
                mma16(c[nt], qh[s], bl);
                mma16(c[nt], ql[s], bh);
            }
        }

        // online softmax (rows g, g+8); score = 0.125 * c
        float alpha[2];
#pragma unroll
        for (int r = 0; r < 2; r++) {
            const int e0 = r * 2;
            float mx = -1e30f;
#pragma unroll
            for (int nt = 0; nt < 8; nt++)
                mx = fmaxf(mx, fmaxf(c[nt][e0], c[nt][e0 + 1]));
            mx = fmaxf(mx, __shfl_xor_sync(0xffffffffu, mx, 1));
            mx = fmaxf(mx, __shfl_xor_sync(0xffffffffu, mx, 2));
            const float mn = fmaxf(mi[r], mx * 0.125f);
            alpha[r] = __expf(mi[r] - mn);
            mi[r] = mn;
            float rs = 0.0f;
#pragma unroll
            for (int nt = 0; nt < 8; nt++) {
                float p0 = __expf(fmaf(c[nt][e0], 0.125f, -mn));
                float p1 = __expf(fmaf(c[nt][e0 + 1], 0.125f, -mn));
                c[nt][e0] = p0; c[nt][e0 + 1] = p1;
                rs += p0 + p1;
            }
            rs += __shfl_xor_sync(0xffffffffu, rs, 1);
            rs += __shfl_xor_sync(0xffffffffu, rs, 2);
            li[r] = li[r] * alpha[r] + rs;
#pragma unroll
            for (int nt = 0; nt < 8; nt++) {
                o[nt][e0]     *= alpha[r];
                o[nt][e0 + 1] *= alpha[r];
            }
        }

        // O += P V : P packs directly from C regs into A fragments
#pragma unroll
        for (int s = 0; s < 4; s++) {
            unsigned ph[4], pl[4];
            {
                float x0 = c[2 * s][0], x1 = c[2 * s][1];
                float h0 = bhi(x0), h1 = bhi(x1);
                ph[0] = bpack(h0, h1); pl[0] = bpack(x0 - h0, x1 - h1);
                x0 = c[2 * s][2]; x1 = c[2 * s][3];
                h0 = bhi(x0); h1 = bhi(x1);
                ph[1] = bpack(h0, h1); pl[1] = bpack(x0 - h0, x1 - h1);
                x0 = c[2 * s + 1][0]; x1 = c[2 * s + 1][1];
                h0 = bhi(x0); h1 = bhi(x1);
                ph[2] = bpack(h0, h1); pl[2] = bpack(x0 - h0, x1 - h1);
                x0 = c[2 * s + 1][2]; x1 = c[2 * s + 1][3];
                h0 = bhi(x0); h1 = bhi(x1);
                ph[3] = bpack(h0, h1); pl[3] = bpack(x0 - h0, x1 - h1);
            }
            const int kb = s * 8;   // token-pair base
#pragma unroll
            for (int nt = 0; nt < 8; nt++) {
                const int nb = nt * 8 + g;
                unsigned bh[2], bl[2];
                bh[0] = Vsh[(kb + tig) * 72 + nb];
                bh[1] = Vsh[(kb + 4 + tig) * 72 + nb];
                bl[0] = Vsl[(kb + tig) * 72 + nb];
                bl[1] = Vsl[(kb + 4 + tig) * 72 + nb];
                mma16(o[nt], ph, bh);
                mma16(o[nt], ph, bl);
                mma16(o[nt], pl, bh);
            }
        }
    }

    // epilogue: normalize and write to (B,N,D) context buffer
    float* Cg = g_Ctx + ((size_t)b * SEQ + q0 + 16 * w) * DMODEL + h * HDIM;
#pragma unroll
    for (int r = 0; r < 2; r++) {
        const float inv = 1.0f / li[r];
        float* rp = Cg + (size_t)(g + 8 * r) * DMODEL;
#pragma unroll
        for (int nt = 0; nt < 8; nt++)
            *(float2*)(rp + nt * 8 + 2 * tig) =
                make_float2(o[nt][r * 2] * inv, o[nt][r * 2 + 1] * inv);
    }
}

// ---------------------------------------------------------------------------
extern "C" void kernel_launch(void* const* d_in, const int* in_sizes, int n_in,
                              void* d_out, int out_size)
{
    const float* x     = (const float*)d_in[0];
    const float* bias  = (const float*)d_in[1];
    const float* Wqkv  = (const float*)d_in[2];
    const float* bqkv  = (const float*)d_in[3];
    const float* Wproj = (const float*)d_in[4];
    const float* bproj = (const float*)d_in[5];
    float* out = (float*)d_out;

    cudaFuncSetAttribute(attn_tc,
                         cudaFuncAttributeMaxDynamicSharedMemorySize, AT_SMEM);

    {
        dim3 grid(N_QKV / 64, M_TOT / 128);
        gemm_tc<0><<<grid, 256>>>(x, Wqkv, bqkv, nullptr, N_QKV, DMODEL);
    }
    {
        dim3 grid(SEQ / 128, NH, BB);
        attn_tc<<<grid, 256, AT_SMEM>>>(bias);
    }
    {
        dim3 grid(DMODEL / 64, M_TOT / 128);
        gemm_tc<1><<<grid, 256>>>(nullptr, Wproj, bproj, out, DMODEL, DMODEL);
    }
}